// round 6
// baseline (speedup 1.0000x reference)
#include <cuda_runtime.h>
#include <cuda_fp16.h>
#include <math.h>

// Problem constants (B=1, C=256, H=64, W=96, R=4)
#define Hh 64
#define Ww 96
#define Cc 256
#define HW (Hh * Ww)          // 6144
#define KK 9
#define NOUT (KK * KK)        // 81

// Spatial bucketing: 4x4-pixel centroid tiles
#define NTX 24                // 96/4
#define NTY 16                // 64/4
#define NTILES (NTX * NTY)    // 384
#define CAP 256               // queries per tile capacity (mean ~16)
#define RR 13                 // tile region edge: 4 + 9
#define NCOLS (RR * RR)       // 169 columns per tile region

// Pixel-major fp16 copies: g_f*h[pixel][channel]
__device__ __half g_f1h[HW * Cc];
__device__ __half g_f2h[HW * Cc];
__device__ int g_cnt[NTILES];
__device__ int g_list[NTILES * CAP];

// --------------------------------------------------------------------------
// Transpose+convert both maps: [C, HW] fp32 -> [HW, C] fp16. Also zeroes the
// bucket counters. grid (192, 8, 2), block (32, 8); 4 elements per thread.
// --------------------------------------------------------------------------
__global__ __launch_bounds__(256) void transpose_convert(const float* __restrict__ f1,
                                                         const float* __restrict__ f2) {
    __shared__ float tile[32][33];
    const float* in = blockIdx.z ? f2 : f1;
    __half* outh = blockIdx.z ? g_f2h : g_f1h;
    const int p0 = blockIdx.x * 32;
    const int c0 = blockIdx.y * 32;
    const int tx = threadIdx.x, ty = threadIdx.y;

    if (blockIdx.z == 0 && blockIdx.y == 0 && blockIdx.x < 2) {
        const int i = blockIdx.x * 256 + ty * 32 + tx;
        if (i < NTILES) g_cnt[i] = 0;
    }

    #pragma unroll
    for (int i = 0; i < 4; ++i)                       // coalesced along pixels
        tile[ty + 8 * i][tx] = in[(c0 + ty + 8 * i) * HW + p0 + tx];
    __syncthreads();
    #pragma unroll
    for (int i = 0; i < 4; ++i) {                     // coalesced along channels
        const int pr = ty + 8 * i;
        outh[(size_t)(p0 + pr) * Cc + (c0 + tx)] = __float2half(tile[tx][pr]);
    }
}

// --------------------------------------------------------------------------
// Bucket queries by floor(centroid) tile. grid 24, block 256.
// --------------------------------------------------------------------------
__global__ __launch_bounds__(256) void bucket_kernel(const float* __restrict__ coords) {
    const int q = blockIdx.x * 256 + threadIdx.x;
    const float cx = coords[q];
    const float cy = coords[HW + q];
    const int fx = min(max((int)floorf(cx), 0), Ww - 1);
    const int fy = min(max((int)floorf(cy), 0), Hh - 1);
    const int tile = (fy >> 2) * NTX + (fx >> 2);
    const int slot = atomicAdd(&g_cnt[tile], 1);
    if (slot < CAP) g_list[tile * CAP + slot] = q;
}

// --------------------------------------------------------------------------
// Main: one block per tile. Load 169 fmap2 columns (fp16, 86.5 KB) into smem
// once, then warps process the tile's queries from smem (LDS, not LDG).
// Per query: 25 passes x (4 columns, 8 lanes/column, HFMA2), 11x12 zero-
// guarded window, 81 bilinear combines, scattered store.
// --------------------------------------------------------------------------
#define SMEM_MAIN (NCOLS * Cc * 2 + 8 * 132 * 4)      // 86528 + 4224 = 90752

__global__ __launch_bounds__(256) void corr_main(const float* __restrict__ coords,
                                                 float* __restrict__ out) {
    extern __shared__ __align__(16) char smem_raw[];
    __half* tileh = (__half*)smem_raw;                   // [NCOLS][Cc]
    float* winb = (float*)(smem_raw + NCOLS * Cc * 2);   // [8][132]

    const int t = threadIdx.x, warp = t >> 5, lane = t & 31;
    const int tid = blockIdx.x;
    const int nq = g_cnt[tid];
    if (nq == 0) return;
    const int tix = tid % NTX, tiy = tid / NTX;
    const int x0 = tix * 4 - 4, y0 = tiy * 4 - 4;

    // ---- Load tile region: 169 columns x 512B, clamped (OOB stays finite)
    {
        uint4* dst = (uint4*)tileh;
        const uint4* src = (const uint4*)g_f2h;
        for (int i = t; i < NCOLS * 32; i += 256) {
            const int col = i >> 5, v = i & 31;
            const int lx = col % RR, ly = col / RR;
            const int xx = min(max(x0 + lx, 0), Ww - 1);
            const int yy = min(max(y0 + ly, 0), Hh - 1);
            dst[i] = src[(size_t)(yy * Ww + xx) * 32 + v];
        }
    }
    __syncthreads();

    const int g = lane & 7;        // channel chunk within column
    const int colsel = lane >> 3;  // which of 4 columns per pass
    float* w = winb + warp * 132;
    const uint4* tq = (const uint4*)tileh;

    for (int base = 0; base < nq; base += 8) {
        const int qi = base + warp;
        const bool active = qi < nq;
        const int q = g_list[tid * CAP + (active ? qi : 0)];

        const float cx = coords[q];
        const float cy = coords[HW + q];
        const int xb = (int)floorf(cx) - 4;
        const int yb = (int)floorf(cy) - 4;
        const int wcol0 = (yb - y0) * RR + (xb - x0);   // 0..42

        // A: lane's 32 channels of query vector (coalesced; groups broadcast)
        const uint4* aq = (const uint4*)g_f1h + (size_t)q * 32 + g;
        const uint4 av0 = aq[0], av1 = aq[8], av2 = aq[16], av3 = aq[24];
        const __half2* A0 = (const __half2*)&av0;
        const __half2* A1 = (const __half2*)&av1;
        const __half2* A2 = (const __half2*)&av2;
        const __half2* A3 = (const __half2*)&av3;

        #pragma unroll
        for (int i = lane; i < 132; i += 32) w[i] = 0.0f;
        __syncwarp();

        int iy = 0, jx = colsel;
        #pragma unroll 1
        for (int p = 0; p < 25; ++p) {
            const uint4* col = tq + (wcol0 + iy * RR + jx) * 32 + g;
            const uint4 c0 = col[0], c1 = col[8], c2 = col[16], c3 = col[24];
            const bool ok = ((unsigned)(yb + iy) < (unsigned)Hh)
                          & ((unsigned)(xb + jx) < (unsigned)Ww);

            const __half2* b0 = (const __half2*)&c0;
            const __half2* b1 = (const __half2*)&c1;
            const __half2* b2 = (const __half2*)&c2;
            const __half2* b3 = (const __half2*)&c3;

            __half2 acc0 = __hmul2(b0[0], A0[0]);
            __half2 acc1 = __hmul2(b0[1], A0[1]);
            __half2 acc2 = __hmul2(b0[2], A0[2]);
            __half2 acc3 = __hmul2(b0[3], A0[3]);
            acc0 = __hfma2(b1[0], A1[0], acc0);
            acc1 = __hfma2(b1[1], A1[1], acc1);
            acc2 = __hfma2(b1[2], A1[2], acc2);
            acc3 = __hfma2(b1[3], A1[3], acc3);
            acc0 = __hfma2(b2[0], A2[0], acc0);
            acc1 = __hfma2(b2[1], A2[1], acc1);
            acc2 = __hfma2(b2[2], A2[2], acc2);
            acc3 = __hfma2(b2[3], A2[3], acc3);
            acc0 = __hfma2(b3[0], A3[0], acc0);
            acc1 = __hfma2(b3[1], A3[1], acc1);
            acc2 = __hfma2(b3[2], A3[2], acc2);
            acc3 = __hfma2(b3[3], A3[3], acc3);

            const __half2 t0 = __hadd2(acc0, acc1);
            const __half2 t1 = __hadd2(acc2, acc3);
            const float2 fv = __half22float2(__hadd2(t0, t1));
            float s = fv.x + fv.y;

            s += __shfl_xor_sync(0xffffffffu, s, 1);
            s += __shfl_xor_sync(0xffffffffu, s, 2);
            s += __shfl_xor_sync(0xffffffffu, s, 4);
            if (g == 0) w[iy * 12 + jx] = s * (ok ? 0.0625f : 0.0f);

            jx += 4;
            if (jx >= 10) { jx -= 10; ++iy; }
        }
        __syncwarp();

        // Bilinear gather of the 81 outputs (i offsets x, j offsets y)
        if (active) {
            #pragma unroll
            for (int k = lane; k < NOUT; k += 32) {
                const int i = k / KK;
                const int j = k - i * KK;
                const float x = cx + (float)(i - 4);
                const float y = cy + (float)(j - 4);
                const float xf = floorf(x);
                const float yf = floorf(y);
                const int ix = (int)xf - xb;   // 0..9 (+1 guard)
                const int iw = (int)yf - yb;   // 0..9 (+1 guard)
                const float wx1 = x - xf, wy1 = y - yf;
                const float wx0 = 1.0f - wx1, wy0 = 1.0f - wy1;
                const float* r0 = w + iw * 12 + ix;
                const float* r1 = r0 + 12;
                out[(size_t)k * HW + q] = wy0 * (wx0 * r0[0] + wx1 * r0[1])
                                        + wy1 * (wx0 * r1[0] + wx1 * r1[1]);
            }
        }
        __syncwarp();
    }
}

// --------------------------------------------------------------------------
extern "C" void kernel_launch(void* const* d_in, const int* in_sizes, int n_in,
                              void* d_out, int out_size) {
    const float* fmap1  = (const float*)d_in[0];
    const float* fmap2  = (const float*)d_in[1];
    const float* coords = (const float*)d_in[2];
    float* out = (float*)d_out;

    cudaFuncSetAttribute(corr_main, cudaFuncAttributeMaxDynamicSharedMemorySize,
                         SMEM_MAIN);

    transpose_convert<<<dim3(192, 8, 2), dim3(32, 8)>>>(fmap1, fmap2);
    bucket_kernel<<<HW / 256, 256>>>(coords);
    corr_main<<<NTILES, 256, SMEM_MAIN>>>(coords, out);
}

// round 8
// speedup vs baseline: 1.6901x; 1.6901x over previous
#include <cuda_runtime.h>
#include <cuda_fp16.h>
#include <stdint.h>
#include <math.h>

// Problem constants (B=1, C=256, H=64, W=96, R=4)
#define Hh 64
#define Ww 96
#define Cc 256
#define HW (Hh * Ww)          // 6144
#define KK 9
#define NOUT (KK * KK)        // 81

// Spatial bucketing: 4x4-pixel centroid tiles
#define NTX 24
#define NTY 16
#define NTILES (NTX * NTY)    // 384
#define CAP 256
#define RR 13                 // region edge: 4 + 9
#define NCOLS (RR * RR)       // 169 region columns
#define MPAD 176              // 11 x m16 tiles
#define NQ 32                 // queries per MMA round (4 x n8 tiles)

// Pixel-major fp16 copies: g_f*h[pixel][channel]
__device__ __half g_f1h[HW * Cc];
__device__ __half g_f2h[HW * Cc];
__device__ int g_cnt[NTILES];
__device__ int g_list[NTILES * CAP];

// --------------------------------------------------------------------------
// Transpose+convert both maps: [C, HW] fp32 -> [HW, C] fp16; zero counters.
// --------------------------------------------------------------------------
__global__ __launch_bounds__(256) void transpose_convert(const float* __restrict__ f1,
                                                         const float* __restrict__ f2) {
    __shared__ float tile[32][33];
    const float* in = blockIdx.z ? f2 : f1;
    __half* outh = blockIdx.z ? g_f2h : g_f1h;
    const int p0 = blockIdx.x * 32;
    const int c0 = blockIdx.y * 32;
    const int tx = threadIdx.x, ty = threadIdx.y;

    if (blockIdx.z == 0 && blockIdx.y == 0 && blockIdx.x < 2) {
        const int i = blockIdx.x * 256 + ty * 32 + tx;
        if (i < NTILES) g_cnt[i] = 0;
    }

    #pragma unroll
    for (int i = 0; i < 4; ++i)
        tile[ty + 8 * i][tx] = in[(c0 + ty + 8 * i) * HW + p0 + tx];
    __syncthreads();
    #pragma unroll
    for (int i = 0; i < 4; ++i) {
        const int pr = ty + 8 * i;
        outh[(size_t)(p0 + pr) * Cc + (c0 + tx)] = __float2half(tile[tx][pr]);
    }
}

// --------------------------------------------------------------------------
// Bucket queries by floor(centroid) 4x4 tile.
// --------------------------------------------------------------------------
__global__ __launch_bounds__(256) void bucket_kernel(const float* __restrict__ coords) {
    const int q = blockIdx.x * 256 + threadIdx.x;
    const float cx = coords[q];
    const float cy = coords[HW + q];
    const int fx = min(max((int)floorf(cx), 0), Ww - 1);
    const int fy = min(max((int)floorf(cy), 0), Hh - 1);
    const int tile = (fy >> 2) * NTX + (fx >> 2);
    const int slot = atomicAdd(&g_cnt[tile], 1);
    if (slot < CAP) g_list[tile * CAP + slot] = q;
}

// --------------------------------------------------------------------------
// MMA helpers
// --------------------------------------------------------------------------
__device__ __forceinline__ uint32_t swz(uint32_t off) {      // 128B-row swizzle
    return off ^ ((off >> 3) & 0x70);
}
__device__ __forceinline__ void ldsm_x4(unsigned* r, uint32_t addr) {
    asm volatile("ldmatrix.sync.aligned.m8n8.x4.shared.b16 {%0,%1,%2,%3}, [%4];"
        : "=r"(r[0]), "=r"(r[1]), "=r"(r[2]), "=r"(r[3]) : "r"(addr));
}
__device__ __forceinline__ void ldsm_x2(unsigned* r, uint32_t addr) {
    asm volatile("ldmatrix.sync.aligned.m8n8.x2.shared.b16 {%0,%1}, [%2];"
        : "=r"(r[0]), "=r"(r[1]) : "r"(addr));
}
__device__ __forceinline__ void mma16816(float* c, const unsigned* a, const unsigned* b) {
    asm volatile(
        "mma.sync.aligned.m16n8k16.row.col.f32.f16.f16.f32 "
        "{%0,%1,%2,%3}, {%4,%5,%6,%7}, {%8,%9}, {%0,%1,%2,%3};"
        : "+f"(c[0]), "+f"(c[1]), "+f"(c[2]), "+f"(c[3])
        : "r"(a[0]), "r"(a[1]), "r"(a[2]), "r"(a[3]), "r"(b[0]), "r"(b[1]));
}

// Dynamic smem layout (bytes):
//   f2buf: MPAD rows x 128 B (fp16, one 64-ch K-chunk)      = 22528
//   Wbuf : MPAD x 33 f32 (windows, padded stride)           = 23232
//   f1buf: NQ rows x 128 B (fp16, query K-chunk)            =  4096
#define SM_F2 0
#define SM_W  (MPAD * 128)
#define SM_F1 (SM_W + MPAD * 33 * 4)
#define SMEM_MMA (SM_F1 + NQ * 128)        // 49856

// --------------------------------------------------------------------------
// corr_mma: one block (128 thr) per tile. W = F2region[169x256]*F1q[256xNQ]
// via m16n8k16 HMMA, then 81 per-query bilinear combines with per-tap masks.
// --------------------------------------------------------------------------
__global__ __launch_bounds__(128) void corr_mma(const float* __restrict__ coords,
                                                float* __restrict__ out) {
    extern __shared__ __align__(16) char sm[];
    char* f2buf = sm + SM_F2;
    float* Wb = (float*)(sm + SM_W);
    char* f1buf = sm + SM_F1;
    __shared__ float2 qc[NQ];
    __shared__ int qid[NQ];

    const int t = threadIdx.x, lane = t & 31, w = t >> 5;
    const int tid = blockIdx.x;
    const int nq = g_cnt[tid];
    if (nq == 0) return;
    const int tix = tid % NTX, tiy = tid / NTX;
    const int x0 = tix * 4 - 4, y0 = tiy * 4 - 4;

    const uint32_t f2s = (uint32_t)__cvta_generic_to_shared(f2buf);
    const uint32_t f1s = (uint32_t)__cvta_generic_to_shared(f1buf);

    #pragma unroll 1
    for (int rb = 0; rb < nq; rb += NQ) {
        __syncthreads();                        // prior round fully consumed
        if (t < NQ) {                           // stage query meta
            const int qi = rb + t;
            const bool a = qi < nq;
            const int q = g_list[tid * CAP + (a ? qi : 0)];
            qid[t] = a ? q : -1;
            qc[t] = make_float2(coords[q], coords[HW + q]);
        }

        float acc[3][4][4];
        #pragma unroll
        for (int m = 0; m < 3; ++m)
            #pragma unroll
            for (int n = 0; n < 4; ++n)
                #pragma unroll
                for (int e = 0; e < 4; ++e) acc[m][n][e] = 0.0f;

        #pragma unroll 1
        for (int kc = 0; kc < 4; ++kc) {
            __syncthreads();                    // prev chunk consumed / meta ready
            // ---- stage f2 chunk: MPAD x 8 uint4 (clamped region pixels)
            {
                const uint4* src = (const uint4*)g_f2h;
                #pragma unroll
                for (int r = 0; r < 11; ++r) {
                    const int i = t + 128 * r;              // 0..1407
                    const int col = i >> 3, v = i & 7;
                    const int cc2 = min(col, NCOLS - 1);    // pad rows copy col 168
                    const int lx = cc2 % RR, ly = cc2 / RR;
                    const int xx = min(max(x0 + lx, 0), Ww - 1);
                    const int yy = min(max(y0 + ly, 0), Hh - 1);
                    const uint4 d = src[(size_t)(yy * Ww + xx) * 32 + kc * 8 + v];
                    *(uint4*)(f2buf + swz((uint32_t)(col * 128 + v * 16))) = d;
                }
            }
            // ---- stage f1 chunk: NQ x 8 uint4
            {
                const uint4* src = (const uint4*)g_f1h;
                #pragma unroll
                for (int r = 0; r < 2; ++r) {
                    const int i = t + 128 * r;              // 0..255
                    const int qi = i >> 3, v = i & 7;
                    int q = qid[qi]; if (q < 0) q = qid[0];
                    const uint4 d = src[(size_t)q * 32 + kc * 8 + v];
                    *(uint4*)(f1buf + swz((uint32_t)(qi * 128 + v * 16))) = d;
                }
            }
            __syncthreads();

            // ---- MMA: per k16 step, load 4 B-frags then sweep m-tiles
            #pragma unroll
            for (int ks = 0; ks < 4; ++ks) {
                unsigned B[4][2];
                #pragma unroll
                for (int nt = 0; nt < 4; ++nt) {
                    const uint32_t off = (uint32_t)((nt * 8 + (lane & 7)) * 128
                                       + ks * 32 + ((lane >> 3) & 1) * 16);
                    ldsm_x2(B[nt], f1s + swz(off));
                }
                #pragma unroll
                for (int m = 0; m < 3; ++m) {
                    const int mtg = w + 4 * m;
                    if (mtg >= 11) break;
                    unsigned A[4];
                    const uint32_t off = (uint32_t)((mtg * 16 + (lane & 15)) * 128
                                       + ks * 32 + (lane >> 4) * 16);
                    ldsm_x4(A, f2s + swz(off));
                    #pragma unroll
                    for (int nt = 0; nt < 4; ++nt)
                        mma16816(acc[m][nt], A, B[nt]);
                }
            }
        }

        // ---- write W[region col][query] (stride 33 to dodge conflicts)
        #pragma unroll
        for (int m = 0; m < 3; ++m) {
            const int mtg = w + 4 * m;
            if (mtg >= 11) break;
            const int r0 = mtg * 16 + (lane >> 2);
            #pragma unroll
            for (int nt = 0; nt < 4; ++nt) {
                const int c0 = nt * 8 + 2 * (lane & 3);
                Wb[r0 * 33 + c0]           = acc[m][nt][0];
                Wb[r0 * 33 + c0 + 1]       = acc[m][nt][1];
                Wb[(r0 + 8) * 33 + c0]     = acc[m][nt][2];
                Wb[(r0 + 8) * 33 + c0 + 1] = acc[m][nt][3];
            }
        }
        __syncthreads();

        // ---- bilinear: 81 outputs x NQ queries, per-tap validity masks
        for (int i = t; i < NOUT * NQ; i += 128) {
            const int qi = i & (NQ - 1);
            const int kk = i >> 5;
            const int q = qid[qi];
            if (q < 0) continue;
            const float cx = qc[qi].x, cy = qc[qi].y;
            const int io = kk / KK;          // offsets x (meshgrid 'ij' quirk)
            const int jo = kk - io * KK;     // offsets y
            const float x = cx + (float)(io - 4);
            const float y = cy + (float)(jo - 4);
            const float xf = floorf(x), yf = floorf(y);
            const int xt = (int)xf, yt = (int)yf;
            const float wx1 = x - xf, wy1 = y - yf;
            const float wx0 = 1.0f - wx1, wy0 = 1.0f - wy1;
            const int wr = (yt - y0) * RR + (xt - x0);   // in [0,168] always
            const float m00 = ((unsigned)xt < 96u) & ((unsigned)yt < 64u) ? 1.f : 0.f;
            const float m10 = ((unsigned)(xt + 1) < 96u) & ((unsigned)yt < 64u) ? 1.f : 0.f;
            const float m01 = ((unsigned)xt < 96u) & ((unsigned)(yt + 1) < 64u) ? 1.f : 0.f;
            const float m11 = ((unsigned)(xt + 1) < 96u) & ((unsigned)(yt + 1) < 64u) ? 1.f : 0.f;
            const float* base = Wb + wr * 33 + qi;
            const float v = wy0 * (wx0 * m00 * base[0] + wx1 * m10 * base[33])
                          + wy1 * (wx0 * m01 * base[RR * 33] + wx1 * m11 * base[RR * 33 + 33]);
            out[(size_t)kk * HW + q] = v * 0.0625f;      // / sqrt(256)
        }
    }
}

// --------------------------------------------------------------------------
extern "C" void kernel_launch(void* const* d_in, const int* in_sizes, int n_in,
                              void* d_out, int out_size) {
    const float* fmap1  = (const float*)d_in[0];
    const float* fmap2  = (const float*)d_in[1];
    const float* coords = (const float*)d_in[2];
    float* out = (float*)d_out;

    cudaFuncSetAttribute(corr_mma, cudaFuncAttributeMaxDynamicSharedMemorySize,
                         SMEM_MMA);

    transpose_convert<<<dim3(192, 8, 2), dim3(32, 8)>>>(fmap1, fmap2);
    bucket_kernel<<<HW / 256, 256>>>(coords);
    corr_mma<<<NTILES, 128, SMEM_MMA>>>(coords, out);
}

// round 9
// speedup vs baseline: 2.0144x; 1.1918x over previous
#include <cuda_runtime.h>
#include <cuda_fp16.h>
#include <stdint.h>
#include <math.h>

// Problem constants (B=1, C=256, H=64, W=96, R=4)
#define Hh 64
#define Ww 96
#define Cc 256
#define HW (Hh * Ww)          // 6144
#define KK 9
#define NOUT (KK * KK)        // 81

// Spatial bucketing: 4x4-pixel centroid tiles
#define NTX 24
#define NTY 16
#define NTILES (NTX * NTY)    // 384
#define CAP 256
#define RR 13                 // region edge: 4 + 9
#define NCOLS (RR * RR)       // 169 region columns
#define MPAD 176              // 11 x m16 tiles
#define NQ 32                 // queries per MMA round (4 x n8 tiles)

// Pixel-major fp16 copies: g_f*h[pixel][channel]
__device__ __half g_f1h[HW * Cc];
__device__ __half g_f2h[HW * Cc];
__device__ int g_cnt[NTILES];
__device__ int g_list[NTILES * CAP];

// --------------------------------------------------------------------------
// Transpose+convert v2: 64x64 tiles, float4 in / uint4(8 half) out.
// grid (96, 4, 2), block 256. Also zeroes bucket counters.
// --------------------------------------------------------------------------
__global__ __launch_bounds__(256) void transpose_convert(const float* __restrict__ f1,
                                                         const float* __restrict__ f2) {
    __shared__ float tile[64][65];
    const float* in = blockIdx.z ? f2 : f1;
    __half* outh = blockIdx.z ? g_f2h : g_f1h;
    const int p0 = blockIdx.x * 64;
    const int c0 = blockIdx.y * 64;
    const int t = threadIdx.x;

    if (blockIdx.z == 0 && blockIdx.y == 0 && blockIdx.x < 2) {
        const int i = blockIdx.x * 256 + t;
        if (i < NTILES) g_cnt[i] = 0;
    }

    {   // load: 64 channel-rows x 16 float4 (coalesced along pixels)
        const int j = t & 15;
        const int r0 = t >> 4;
        #pragma unroll
        for (int i = 0; i < 4; ++i) {
            const int r = r0 + 16 * i;
            const float4 v = *(const float4*)(in + (size_t)(c0 + r) * HW + p0 + 4 * j);
            tile[r][4 * j + 0] = v.x;
            tile[r][4 * j + 1] = v.y;
            tile[r][4 * j + 2] = v.z;
            tile[r][4 * j + 3] = v.w;
        }
    }
    __syncthreads();
    {   // store: 64 pixel-rows x 8 uint4 of halves (coalesced along channels)
        const int u = t & 7;
        const int pr0 = t >> 3;
        #pragma unroll
        for (int i = 0; i < 2; ++i) {
            const int pr = pr0 + 32 * i;
            __half h[8];
            #pragma unroll
            for (int e = 0; e < 8; ++e) h[e] = __float2half(tile[8 * u + e][pr]);
            *(uint4*)((char*)outh + ((size_t)(p0 + pr) * Cc + c0) * 2 + u * 16)
                = *(uint4*)h;
        }
    }
}

// --------------------------------------------------------------------------
// Bucket queries by floor(centroid) 4x4 tile.
// --------------------------------------------------------------------------
__global__ __launch_bounds__(256) void bucket_kernel(const float* __restrict__ coords) {
    const int q = blockIdx.x * 256 + threadIdx.x;
    const float cx = coords[q];
    const float cy = coords[HW + q];
    const int fx = min(max((int)floorf(cx), 0), Ww - 1);
    const int fy = min(max((int)floorf(cy), 0), Hh - 1);
    const int tile = (fy >> 2) * NTX + (fx >> 2);
    const int slot = atomicAdd(&g_cnt[tile], 1);
    if (slot < CAP) g_list[tile * CAP + slot] = q;
}

// --------------------------------------------------------------------------
// MMA / cp.async helpers
// --------------------------------------------------------------------------
__device__ __forceinline__ uint32_t swz(uint32_t off) {      // 128B-row swizzle
    return off ^ ((off >> 3) & 0x70);
}
__device__ __forceinline__ void ldsm_x4(unsigned* r, uint32_t addr) {
    asm volatile("ldmatrix.sync.aligned.m8n8.x4.shared.b16 {%0,%1,%2,%3}, [%4];"
        : "=r"(r[0]), "=r"(r[1]), "=r"(r[2]), "=r"(r[3]) : "r"(addr));
}
__device__ __forceinline__ void ldsm_x2(unsigned* r, uint32_t addr) {
    asm volatile("ldmatrix.sync.aligned.m8n8.x2.shared.b16 {%0,%1}, [%2];"
        : "=r"(r[0]), "=r"(r[1]) : "r"(addr));
}
__device__ __forceinline__ void mma16816(float* c, const unsigned* a, const unsigned* b) {
    asm volatile(
        "mma.sync.aligned.m16n8k16.row.col.f32.f16.f16.f32 "
        "{%0,%1,%2,%3}, {%4,%5,%6,%7}, {%8,%9}, {%0,%1,%2,%3};"
        : "+f"(c[0]), "+f"(c[1]), "+f"(c[2]), "+f"(c[3])
        : "r"(a[0]), "r"(a[1]), "r"(a[2]), "r"(a[3]), "r"(b[0]), "r"(b[1]));
}
__device__ __forceinline__ void cp16(uint32_t dst, const void* src) {
    asm volatile("cp.async.cg.shared.global [%0], [%1], 16;" :: "r"(dst), "l"(src));
}
__device__ __forceinline__ void cp_commit() {
    asm volatile("cp.async.commit_group;");
}
template <int N> __device__ __forceinline__ void cp_wait() {
    asm volatile("cp.async.wait_group %0;" :: "n"(N));
}

// Dynamic smem layout (bytes, all 1024-aligned):
//   f2buf[3]: 3 x MPAD x 128 B  (triple-buffered K-chunks)   = 67584
//   f1buf   : 4 planes x NQ x 128 B (all K-chunks, staged 1x)= 16384
//   Wbuf    : MPAD x 33 f32                                   = 23232
#define F2BUF_SZ (MPAD * 128)
#define SM_F2 0
#define SM_F1 (3 * F2BUF_SZ)              // 67584
#define SM_W  (SM_F1 + NQ * 512)          // 83968
#define SMEM_MMA (SM_W + MPAD * 33 * 4)   // 107200

// --------------------------------------------------------------------------
// corr_mma v2: one block (256 thr, 8 warps) per tile.
// W[169xNQ] = F2region[169x256] * F1q[256xNQ] via m16n8k16 HMMA with
// cp.async triple-buffered f2 staging; then 81xNQ bilinear combines.
// --------------------------------------------------------------------------
__global__ __launch_bounds__(256) void corr_mma(const float* __restrict__ coords,
                                                float* __restrict__ out) {
    extern __shared__ __align__(16) char sm[];
    float* Wb = (float*)(sm + SM_W);
    __shared__ float2 qc[NQ];
    __shared__ int qid[NQ];

    const int t = threadIdx.x, lane = t & 31, w = t >> 5;
    const int tid = blockIdx.x;
    const int nq = g_cnt[tid];
    if (nq == 0) return;
    const int tix = tid % NTX, tiy = tid / NTX;
    const int x0 = tix * 4 - 4, y0 = tiy * 4 - 4;

    const uint32_t f2s = (uint32_t)__cvta_generic_to_shared(sm + SM_F2);
    const uint32_t f1s = (uint32_t)__cvta_generic_to_shared(sm + SM_F1);

    // stage one f2 K-chunk (64 ch) into buffer b with cp.async
    auto stage_f2 = [&](int kc, int b) {
        #pragma unroll
        for (int r = 0; r < 6; ++r) {
            const int i = t + 256 * r;                 // 0..1535 (use 1408)
            if (i < MPAD * 8) {
                const int col = i >> 3, v = i & 7;
                const int cc2 = min(col, NCOLS - 1);
                const int lx = cc2 % RR, ly = cc2 / RR;
                const int xx = min(max(x0 + lx, 0), Ww - 1);
                const int yy = min(max(y0 + ly, 0), Hh - 1);
                const char* src = (const char*)g_f2h
                    + ((size_t)(yy * Ww + xx) * Cc + kc * 64) * 2 + v * 16;
                cp16(f2s + b * F2BUF_SZ + swz((uint32_t)(col * 128 + v * 16)), src);
            }
        }
    };

    #pragma unroll 1
    for (int rb = 0; rb < nq; rb += NQ) {
        __syncthreads();                       // prior round fully consumed
        if (t < NQ) {
            const int qi = rb + t;
            const bool a = qi < nq;
            const int q = g_list[tid * CAP + (a ? qi : 0)];
            qid[t] = a ? q : -1;
            qc[t] = make_float2(coords[q], coords[HW + q]);
        }
        __syncthreads();                       // qid visible

        // ---- prologue: stage all f1 + f2 chunk0 (group0), f2 chunk1 (group1)
        #pragma unroll
        for (int r = 0; r < 4; ++r) {
            const int i = t + 256 * r;         // 0..1023
            const int qi = i >> 5, v = i & 31;
            const int kc = v >> 3, vv = v & 7;
            int q = qid[qi]; if (q < 0) q = qid[0];
            const char* src = (const char*)g_f1h + (size_t)q * 512 + v * 16;
            cp16(f1s + kc * 4096 + swz((uint32_t)(qi * 128 + vv * 16)), src);
        }
        stage_f2(0, 0);
        cp_commit();
        stage_f2(1, 1);
        cp_commit();

        float acc[2][4][4];
        #pragma unroll
        for (int m = 0; m < 2; ++m)
            #pragma unroll
            for (int n = 0; n < 4; ++n)
                #pragma unroll
                for (int e = 0; e < 4; ++e) acc[m][n][e] = 0.0f;

        // ---- pipelined K loop: MMA chunk kc from buf kc%3, stage kc+2
        #pragma unroll 1
        for (int kc = 0; kc < 4; ++kc) {
            if (kc < 3) cp_wait<1>(); else cp_wait<0>();
            __syncthreads();                   // staged chunk visible; prior buf free
            if (kc + 2 <= 3) {
                stage_f2(kc + 2, (kc + 2) % 3);
                cp_commit();
            }
            const uint32_t f2b = f2s + (kc % 3) * F2BUF_SZ;
            const uint32_t f1p = f1s + kc * 4096;
            #pragma unroll
            for (int ks = 0; ks < 4; ++ks) {
                unsigned B[4][2];
                #pragma unroll
                for (int nt = 0; nt < 4; ++nt)
                    ldsm_x2(B[nt], f1p + swz((uint32_t)((nt * 8 + (lane & 7)) * 128
                                    + ks * 32 + ((lane >> 3) & 1) * 16)));
                unsigned A0[4];
                ldsm_x4(A0, f2b + swz((uint32_t)((w * 16 + (lane & 15)) * 128
                                + ks * 32 + (lane >> 4) * 16)));
                #pragma unroll
                for (int nt = 0; nt < 4; ++nt) mma16816(acc[0][nt], A0, B[nt]);
                if (w < 3) {
                    unsigned A1[4];
                    ldsm_x4(A1, f2b + swz((uint32_t)(((w + 8) * 16 + (lane & 15)) * 128
                                    + ks * 32 + (lane >> 4) * 16)));
                    #pragma unroll
                    for (int nt = 0; nt < 4; ++nt) mma16816(acc[1][nt], A1, B[nt]);
                }
            }
        }

        // ---- write W[region col][query] (stride 33 dodges conflicts)
        #pragma unroll
        for (int m = 0; m < 2; ++m) {
            const int mtg = w + 8 * m;
            if (mtg >= 11) break;
            const int r0 = mtg * 16 + (lane >> 2);
            #pragma unroll
            for (int nt = 0; nt < 4; ++nt) {
                const int c0 = nt * 8 + 2 * (lane & 3);
                Wb[r0 * 33 + c0]           = acc[m][nt][0];
                Wb[r0 * 33 + c0 + 1]       = acc[m][nt][1];
                Wb[(r0 + 8) * 33 + c0]     = acc[m][nt][2];
                Wb[(r0 + 8) * 33 + c0 + 1] = acc[m][nt][3];
            }
        }
        __syncthreads();

        // ---- bilinear: 81 outputs x NQ queries, per-tap validity masks
        for (int i = t; i < NOUT * NQ; i += 256) {
            const int qi = i & (NQ - 1);
            const int kk = i >> 5;
            const int q = qid[qi];
            if (q < 0) continue;
            const float cx = qc[qi].x, cy = qc[qi].y;
            const int io = kk / KK;          // offsets x (meshgrid 'ij' quirk)
            const int jo = kk - io * KK;     // offsets y
            const float x = cx + (float)(io - 4);
            const float y = cy + (float)(jo - 4);
            const float xf = floorf(x), yf = floorf(y);
            const int xt = (int)xf, yt = (int)yf;
            const float wx1 = x - xf, wy1 = y - yf;
            const float wx0 = 1.0f - wx1, wy0 = 1.0f - wy1;
            const int wr = (yt - y0) * RR + (xt - x0);   // in [0,168] always
            const float m00 = ((unsigned)xt < 96u) & ((unsigned)yt < 64u) ? 1.f : 0.f;
            const float m10 = ((unsigned)(xt + 1) < 96u) & ((unsigned)yt < 64u) ? 1.f : 0.f;
            const float m01 = ((unsigned)xt < 96u) & ((unsigned)(yt + 1) < 64u) ? 1.f : 0.f;
            const float m11 = ((unsigned)(xt + 1) < 96u) & ((unsigned)(yt + 1) < 64u) ? 1.f : 0.f;
            const float* base = Wb + wr * 33 + qi;
            const float v = wy0 * (wx0 * m00 * base[0] + wx1 * m10 * base[33])
                          + wy1 * (wx0 * m01 * base[RR * 33] + wx1 * m11 * base[RR * 33 + 33]);
            out[(size_t)kk * HW + q] = v * 0.0625f;      // / sqrt(256)
        }
    }
}

// --------------------------------------------------------------------------
extern "C" void kernel_launch(void* const* d_in, const int* in_sizes, int n_in,
                              void* d_out, int out_size) {
    const float* fmap1  = (const float*)d_in[0];
    const float* fmap2  = (const float*)d_in[1];
    const float* coords = (const float*)d_in[2];
    float* out = (float*)d_out;

    cudaFuncSetAttribute(corr_mma, cudaFuncAttributeMaxDynamicSharedMemorySize,
                         SMEM_MMA);

    transpose_convert<<<dim3(96, 4, 2), 256>>>(fmap1, fmap2);
    bucket_kernel<<<HW / 256, 256>>>(coords);
    corr_mma<<<NTILES, 256, SMEM_MMA>>>(coords, out);
}